// round 15
// baseline (speedup 1.0000x reference)
#include <cuda_runtime.h>
#include <cuda_fp16.h>
#include <cuda.h>
#include <math.h>
#include <stdint.h>

#define NTOK   4096
#define DMODEL 2048
#define MWIDTH 5632
#define NEXP   8
#define RANK   16
#define ERANK  128
#define FSCALE 2.0f

typedef __half h16;

// ---------------- scratch (uint4 => 16B aligned) ----------------
__device__ uint4 g_x_ [(size_t)NTOK*DMODEL/8];                        // x fp16
__device__ uint4 g_wg_[(size_t)MWIDTH*DMODEL/8];
__device__ uint4 g_wu_[(size_t)MWIDTH*DMODEL/8];
__device__ uint4 g_wd_[(size_t)MWIDTH*DMODEL/8];
__device__ uint4 g_h_ [(size_t)NTOK*MWIDTH/8];                        // h fp16
__device__ uint4 g_cg_[NTOK*ERANK/8], g_cu_[NTOK*ERANK/8], g_cd_[NTOK*ERANK/8];
__device__ uint4 g_bg_[MWIDTH*ERANK/8], g_bu_[MWIDTH*ERANK/8];        // flat [n][128]
__device__ uint4 g_bd_[DMODEL*ERANK/8];

// ---------------- helpers ----------------
__device__ __forceinline__ uint32_t s2u(const void* p){
    return (uint32_t)__cvta_generic_to_shared(p);
}
__device__ __forceinline__ uint32_t sw128(uint32_t o){ return o ^ ((o >> 3) & 0x70u); }
__device__ __forceinline__ void mbar_init(uint32_t a, uint32_t cnt){
    asm volatile("mbarrier.init.shared.b64 [%0], %1;" :: "r"(a), "r"(cnt) : "memory");
}
__device__ __forceinline__ void mbar_expect(uint32_t a, uint32_t bytes){
    asm volatile("mbarrier.arrive.expect_tx.shared.b64 _, [%0], %1;"
                 :: "r"(a), "r"(bytes) : "memory");
}
__device__ __forceinline__ void mbar_wait(uint32_t a, uint32_t parity){
    uint32_t done;
    asm volatile("{\n\t.reg .pred p;\n\t"
        "mbarrier.try_wait.parity.acquire.cta.shared::cta.b64 p, [%1], %2;\n\t"
        "selp.b32 %0, 1, 0, p;\n\t}"
        : "=r"(done) : "r"(a), "r"(parity) : "memory");
    if (!done) {
        asm volatile("{\n\t.reg .pred P1;\n\t"
            "W_%=:\n\t"
            "mbarrier.try_wait.parity.acquire.cta.shared::cta.b64 P1, [%0], %1, 0x989680;\n\t"
            "@P1 bra.uni D_%=;\n\t"
            "bra.uni W_%=;\n\t"
            "D_%=:\n\t}"
            :: "r"(a), "r"(parity) : "memory");
    }
}
// 2D TMA tensor copy gmem->smem, completion via mbarrier complete_tx
__device__ __forceinline__ void tma2d(uint32_t dst, const CUtensorMap& tm,
                                      int c0, int c1, uint32_t mbar){
    asm volatile("cp.async.bulk.tensor.2d.shared::cta.global.tile.mbarrier::complete_tx::bytes "
                 "[%0], [%1, {%2, %3}], [%4];"
                 :: "r"(dst), "l"((uint64_t)&tm), "r"(c0), "r"(c1), "r"(mbar) : "memory");
}

#define LDM4(R, A) asm volatile( \
    "ldmatrix.sync.aligned.m8n8.x4.shared.b16 {%0,%1,%2,%3}, [%4];" \
    : "=r"((R)[0]), "=r"((R)[1]), "=r"((R)[2]), "=r"((R)[3]) : "r"(A))

#define MMA(D, A0, A1, A2, A3, B0, B1) asm volatile( \
    "mma.sync.aligned.m16n8k16.row.col.f32.f16.f16.f32 " \
    "{%0,%1,%2,%3}, {%4,%5,%6,%7}, {%8,%9}, {%0,%1,%2,%3};" \
    : "+f"((D)[0]), "+f"((D)[1]), "+f"((D)[2]), "+f"((D)[3]) \
    : "r"(A0), "r"(A1), "r"(A2), "r"(A3), "r"(B0), "r"(B1))

// ---------------- conversion kernels ----------------
__global__ void k_cvtW(const float* __restrict__ i0, h16* __restrict__ o0,
                       const float* __restrict__ i1, h16* __restrict__ o1,
                       const float* __restrict__ i2, h16* __restrict__ o2, int n4){
    const int y = blockIdx.y;
    const float* in = (y == 0) ? i0 : (y == 1) ? i1 : i2;
    h16*         o  = (y == 0) ? o0 : (y == 1) ? o1 : o2;
    int i = blockIdx.x * blockDim.x + threadIdx.x;
    if (i >= n4) return;
    float4 v = ((const float4*)in)[i];
    __half2 p0 = __floats2half2_rn(v.x, v.y);
    __half2 p1 = __floats2half2_rn(v.z, v.w);
    uint2 u{*(uint32_t*)&p0, *(uint32_t*)&p1};
    ((uint2*)o)[i] = u;
}
__global__ void k_bflat(const float* __restrict__ i0, h16* __restrict__ o0,
                        const float* __restrict__ i1, h16* __restrict__ o1,
                        const float* __restrict__ i2, h16* __restrict__ o2){
    const int y = blockIdx.y;
    const float* in = (y == 0) ? i0 : (y == 1) ? i1 : i2;
    h16*         o  = (y == 0) ? o0 : (y == 1) ? o1 : o2;
    const int N = (y == 2) ? DMODEL : MWIDTH;
    const int n = blockIdx.x;
    if (n >= N) return;
    const int j = threadIdx.x;                 // 128 threads
    const int e = j >> 4, r = j & 15;
    o[(size_t)n * ERANK + j] = __float2half_rn(in[((size_t)e * N + n) * RANK + r]);
}

// ---------------- router (+ x fp16 conversion folded in) ----------------
__global__ void k_router(const float* __restrict__ x,  const float* __restrict__ Wr,
                         const float* __restrict__ br, const float* __restrict__ Ag,
                         const float* __restrict__ Au,
                         float* __restrict__ out_routing, float* __restrict__ out_choice)
{
    __shared__ float xs[DMODEL];
    __shared__ float red[40];
    __shared__ float routing_s[NEXP];
    __shared__ int   amax_s;

    const int t = blockIdx.x;
    const float* xrow = x + (size_t)t * DMODEL;
    for (int i = threadIdx.x; i < DMODEL/4; i += blockDim.x)
        ((float4*)xs)[i] = ((const float4*)xrow)[i];
    __syncthreads();

    {
        __half2* xo = (__half2*)((h16*)g_x_ + (size_t)t * DMODEL);
        for (int i = threadIdx.x; i < DMODEL/2; i += blockDim.x)
            xo[i] = __floats2half2_rn(xs[2*i], xs[2*i+1]);
    }

    const int w = threadIdx.x >> 5, lane = threadIdx.x & 31;
    #pragma unroll
    for (int q = 0; q < 5; ++q) {
        const int o = w + 8*q;
        const float* wrow = (o < 8)  ? (Wr + o*DMODEL)
                          : (o < 24) ? (Ag + (o-8)*DMODEL)
                                     : (Au + (o-24)*DMODEL);
        float s = 0.f;
        for (int k = lane; k < DMODEL; k += 32) s = fmaf(xs[k], wrow[k], s);
        #pragma unroll
        for (int off = 16; off; off >>= 1) s += __shfl_xor_sync(0xffffffffu, s, off);
        if (lane == 0) red[o] = s;
    }
    __syncthreads();

    if (threadIdx.x == 0) {
        float lg[NEXP]; float mx = -1e30f;
        #pragma unroll
        for (int e = 0; e < NEXP; ++e){ lg[e] = red[e] + br[e]; mx = fmaxf(mx, lg[e]); }
        float sum = 0.f;
        #pragma unroll
        for (int e = 0; e < NEXP; ++e){ lg[e] = expf(lg[e]-mx); sum += lg[e]; }
        const float inv = 1.f/sum;
        int am = 0; float best = -1.f;
        #pragma unroll
        for (int e = 0; e < NEXP; ++e){
            const float r = lg[e]*inv; routing_s[e] = r;
            if (r > best){ best = r; am = e; }
        }
        amax_s = am;
    }
    __syncthreads();

    if (threadIdx.x < NEXP) {
        const float r = routing_s[threadIdx.x];
        out_routing[t*NEXP + threadIdx.x] = r;
        const float yh = (threadIdx.x == amax_s) ? 1.f : 0.f;
        out_choice[t*NEXP + threadIdx.x] = (yh - r) + r;
    }
    const int j = threadIdx.x & 127;
    const int e = j >> 4, rr = j & 15;
    if (threadIdx.x < 128)
        ((h16*)g_cg_)[(size_t)t*ERANK + j] = __float2half_rn(routing_s[e]*red[8+rr]*FSCALE);
    else
        ((h16*)g_cu_)[(size_t)t*ERANK + j] = __float2half_rn(routing_s[e]*red[24+rr]*FSCALE);
}

// ---------------- h @ Ad^T -> c_d  (one block per token) ----------------
__global__ void k_hd(const float* __restrict__ Ad, const float* __restrict__ routing)
{
    __shared__ float hs[MWIDTH];
    __shared__ float red[RANK];
    const int t = blockIdx.x;
    const h16* hrow = (const h16*)g_h_ + (size_t)t * MWIDTH;
    for (int i = threadIdx.x; i < MWIDTH/2; i += blockDim.x){
        __half2 v = ((const __half2*)hrow)[i];
        float2 f = __half22float2(v);
        hs[2*i] = f.x; hs[2*i+1] = f.y;
    }
    __syncthreads();

    const int w = threadIdx.x >> 5, lane = threadIdx.x & 31;
    #pragma unroll
    for (int q = 0; q < 2; ++q) {
        const int r = w*2 + q;
        const float* arow = Ad + (size_t)r * MWIDTH;
        float s = 0.f;
        for (int k = lane; k < MWIDTH; k += 32) s = fmaf(hs[k], arow[k], s);
        #pragma unroll
        for (int off = 16; off; off >>= 1) s += __shfl_xor_sync(0xffffffffu, s, off);
        if (lane == 0) red[r] = s;
    }
    __syncthreads();
    if (threadIdx.x < 128) {
        const int e = threadIdx.x >> 4, rr = threadIdx.x & 15;
        ((h16*)g_cd_)[(size_t)t*ERANK + threadIdx.x]
            = __float2half_rn(routing[t*NEXP + e] * red[rr] * FSCALE);
    }
}

// ---------------- fp16 mma.sync GEMM, 2D-TMA loads, 2 CTAs/SM ----------------
// Inner loop register double-buffers A/B0 fragments: LDM4s for ks+1 are issued
// before the MMAs of ks, so LDSM latency hides under tensor work.
// DUAL : BM=128 BN=64,  A=x,  B0=Wg->accG, B1=Wu->accU (+aug cg/Bg, cu/Bu),
//        epilogue silu(g)*u -> g_h_ (fp16)
// !DUAL: BM=128 BN=128, A=h,  B0=Wd (+aug cd/Bd), epilogue -> fp32 out
template<bool DUAL>
__global__ __launch_bounds__(256, 2)
void k_mma(float* __restrict__ OutP,
           const __grid_constant__ CUtensorMap tmA,
           const __grid_constant__ CUtensorMap tmB0,
           const __grid_constant__ CUtensorMap tmB1,
           const __grid_constant__ CUtensorMap tmCA,
           const __grid_constant__ CUtensorMap tmCA2,
           const __grid_constant__ CUtensorMap tmBA,
           const __grid_constant__ CUtensorMap tmBA2)
{
    constexpr int PA     = 16384;                       // A plane: 128 rows x 128B
    constexpr int BN     = DUAL ? 64 : 128;
    constexpr int PB     = BN * 128;                    // 8192 / 16384
    constexpr int STAGEB = PA + (DUAL ? 2 : 1) * PB;    // 32768 both
    constexpr int JN     = DUAL ? 4 : 8;
    constexpr int JH     = JN / 2;                      // B0 LDM4s per ks
    constexpr int WTN    = DUAL ? 32 : 64;
    constexpr int NKM    = DUAL ? (DMODEL/64) : (MWIDTH/64);  // 32 / 88
    constexpr int NT     = DUAL ? (NKM + 4) : (NKM + 2);

    __shared__ __align__(8) uint64_t mbs[3];
    extern __shared__ __align__(16) char smem[];
    const uint32_t sb  = (s2u(smem) + 1023u) & ~1023u;   // 1024-align for SW128 atoms
    const uint32_t mbb = s2u(mbs);
    const int tid = threadIdx.x, wid = tid >> 5, lane = tid & 31;
    const int wm = wid & 3, wn = wid >> 2;
    const int m0 = (DUAL ? blockIdx.x : blockIdx.y) * 128;
    const int n0 = (DUAL ? blockIdx.y : blockIdx.x) * BN;

    if (tid < 3) mbar_init(mbb + tid*8, 1);
    __syncthreads();

    float accG[2][JN][4];
    float accU[DUAL?2:1][DUAL?JN:1][4];
    #pragma unroll
    for (int m=0;m<2;++m) for (int j=0;j<JN;++j) for (int q=0;q<4;++q) accG[m][j][q]=0.f;
    if constexpr (DUAL){
        #pragma unroll
        for (int m=0;m<2;++m) for (int j=0;j<JN;++j) for (int q=0;q<4;++q) accU[m][j][q]=0.f;
    }

    // hoisted swizzled base offsets (kb folded in later by XOR)
    const uint32_t lanehi = (uint32_t)((lane >> 4) << 4);
    const uint32_t offA0 = sw128((uint32_t)((wm*32      + (lane & 15)) * 128) + lanehi);
    const uint32_t offA1 = sw128((uint32_t)((wm*32 + 16 + (lane & 15)) * 128) + lanehi);
    uint32_t offB[JH];
    #pragma unroll
    for (int g = 0; g < JH; ++g)
        offB[g] = sw128((uint32_t)((wn*WTN + g*16 + (lane & 15)) * 128) + lanehi);

    // single-thread tile load: expect_tx + 2-3 TMA 2D requests
    auto load_tile = [&](int kt){
        const uint32_t st  = sb  + (uint32_t)(kt % 3) * STAGEB;
        const uint32_t mb_ = mbb + (uint32_t)(kt % 3) * 8;
        if (kt < NKM){
            const int ko = kt * 64;
            mbar_expect(mb_, (uint32_t)STAGEB);
            tma2d(st,       tmA,  ko, m0, mb_);
            tma2d(st + PA,  tmB0, ko, n0, mb_);
            if constexpr (DUAL) tma2d(st + PA + PB, tmB1, ko, n0, mb_);
        } else {
            const bool gsel = !DUAL || (kt < NKM + 2);
            const int ko = (kt - NKM - ((DUAL && !gsel) ? 2 : 0)) * 64;
            mbar_expect(mb_, (uint32_t)(PA + PB));
            tma2d(st,      gsel ? tmCA : tmCA2, ko, m0, mb_);
            tma2d(st + PA, gsel ? tmBA : tmBA2, ko, n0, mb_);
        }
    };

    if (tid == 0){ load_tile(0); load_tile(1); }

    // parity-alternating fragment registers
    uint32_t aP[2][2][4];
    uint32_t bP[2][JH][4];

    for (int kt = 0; kt < NT; ++kt){
        mbar_wait(mbb + (uint32_t)(kt % 3)*8, (kt/3) & 1);   // tile kt landed
        __syncthreads();                     // all warps done reading stage (kt-1)%3
        if (kt + 2 < NT && tid == 0) load_tile(kt + 2);

        const uint32_t st = sb + (uint32_t)(kt % 3) * STAGEB;
        const uint32_t bA0 = st + offA0, bA1 = st + offA1;
        uint32_t bB0[JH], bB1[DUAL ? JH : 1];
        #pragma unroll
        for (int g = 0; g < JH; ++g) bB0[g] = st + PA + offB[g];
        if constexpr (DUAL){
            #pragma unroll
            for (int g = 0; g < JH; ++g) bB1[g] = st + PA + PB + offB[g];
        }
        // mode: 0 main, 1 aug->accG, 2 aug->accU
        int mode = 0;
        if (kt >= NKM) mode = (DUAL && kt >= NKM+2) ? 2 : 1;

        // preload ks=0 fragments
        LDM4(aP[0][0], bA0);
        LDM4(aP[0][1], bA1);
        #pragma unroll
        for (int g = 0; g < JH; ++g) LDM4(bP[0][g], bB0[g]);

        #pragma unroll
        for (int ks = 0; ks < 4; ++ks){
            const int cur = ks & 1, nxt = cur ^ 1;
            // issue next-ks fragment loads BEFORE the MMAs of this ks
            if (ks < 3){
                const uint32_t kb = (uint32_t)((ks + 1) * 32);
                LDM4(aP[nxt][0], bA0 ^ kb);
                LDM4(aP[nxt][1], bA1 ^ kb);
                #pragma unroll
                for (int g = 0; g < JH; ++g) LDM4(bP[nxt][g], bB0[g] ^ kb);
            }
            const uint32_t (*a0)[4] = &aP[cur][0];
            if (mode != 2){
                #pragma unroll
                for (int j = 0; j < JN; ++j){
                    const uint32_t bx = bP[cur][j>>1][j&1], by = bP[cur][j>>1][(j&1)+2];
                    MMA(accG[0][j], aP[cur][0][0],aP[cur][0][1],aP[cur][0][2],aP[cur][0][3], bx, by);
                    MMA(accG[1][j], aP[cur][1][0],aP[cur][1][1],aP[cur][1][2],aP[cur][1][3], bx, by);
                }
            } else {
                #pragma unroll
                for (int j = 0; j < JN; ++j){
                    const uint32_t bx = bP[cur][j>>1][j&1], by = bP[cur][j>>1][(j&1)+2];
                    MMA(accU[0][j], aP[cur][0][0],aP[cur][0][1],aP[cur][0][2],aP[cur][0][3], bx, by);
                    MMA(accU[1][j], aP[cur][1][0],aP[cur][1][1],aP[cur][1][2],aP[cur][1][3], bx, by);
                }
            }
            if constexpr (DUAL){
                if (mode == 0){
                    const uint32_t kb = (uint32_t)(ks * 32);
                    uint32_t bb1[JH][4];
                    #pragma unroll
                    for (int g = 0; g < JH; ++g) LDM4(bb1[g], bB1[g] ^ kb);
                    #pragma unroll
                    for (int j = 0; j < JN; ++j){
                        const uint32_t bx = bb1[j>>1][j&1], by = bb1[j>>1][(j&1)+2];
                        MMA(accU[0][j], aP[cur][0][0],aP[cur][0][1],aP[cur][0][2],aP[cur][0][3], bx, by);
                        MMA(accU[1][j], aP[cur][1][0],aP[cur][1][1],aP[cur][1][2],aP[cur][1][3], bx, by);
                    }
                }
            }
            (void)a0;
        }
    }

    // ---------------- epilogue ----------------
    #pragma unroll
    for (int m = 0; m < 2; ++m){
        #pragma unroll
        for (int j = 0; j < JN; ++j){
            const int r0 = m0 + wm*32 + m*16 + (lane >> 2);
            const int c0 = n0 + wn*WTN + j*8 + (lane & 3)*2;
            if constexpr (DUAL){
                h16* gh = (h16*)g_h_;
                float hv[4];
                #pragma unroll
                for (int q = 0; q < 4; ++q){
                    const float g = accG[m][j][q], u = accU[m][j][q];
                    hv[q] = g * u / (1.f + __expf(-g));
                }
                *(__half2*)(gh + (size_t)r0*MWIDTH + c0)     = __floats2half2_rn(hv[0], hv[1]);
                *(__half2*)(gh + (size_t)(r0+8)*MWIDTH + c0) = __floats2half2_rn(hv[2], hv[3]);
            } else {
                *(float2*)(OutP + (size_t)r0*DMODEL + c0)
                    = make_float2(accG[m][j][0], accG[m][j][1]);
                *(float2*)(OutP + (size_t)(r0+8)*DMODEL + c0)
                    = make_float2(accG[m][j][2], accG[m][j][3]);
            }
        }
    }
}

// ---------------------------------------------------------------------------
typedef CUresult (*PFN_encodeTiled)(CUtensorMap*, CUtensorMapDataType, cuuint32_t,
    void*, const cuuint64_t*, const cuuint64_t*, const cuuint32_t*, const cuuint32_t*,
    CUtensorMapInterleave, CUtensorMapSwizzle, CUtensorMapL2promotion,
    CUtensorMapFloatOOBfill);

static void make_map(PFN_encodeTiled enc, CUtensorMap* tm, void* base,
                     uint64_t d0, uint64_t d1, uint32_t b0, uint32_t b1){
    cuuint64_t dims[2]    = {d0, d1};
    cuuint64_t strides[1] = {d0 * 2};          // row stride in bytes (fp16)
    cuuint32_t box[2]     = {b0, b1};
    cuuint32_t es[2]      = {1, 1};
    enc(tm, CU_TENSOR_MAP_DATA_TYPE_FLOAT16, 2, base, dims, strides, box, es,
        CU_TENSOR_MAP_INTERLEAVE_NONE, CU_TENSOR_MAP_SWIZZLE_128B,
        CU_TENSOR_MAP_L2_PROMOTION_L2_128B, CU_TENSOR_MAP_FLOAT_OOB_FILL_NONE);
}

extern "C" void kernel_launch(void* const* d_in, const int* in_sizes, int n_in,
                              void* d_out, int out_size)
{
    const float* x  = (const float*)d_in[0];
    const float* Wr = (const float*)d_in[1];
    const float* br = (const float*)d_in[2];
    const float* Wg = (const float*)d_in[3];
    const float* Wu = (const float*)d_in[4];
    const float* Wd = (const float*)d_in[5];
    const float* Ag = (const float*)d_in[6];
    const float* Au = (const float*)d_in[7];
    const float* Ad = (const float*)d_in[8];
    const float* Bg = (const float*)d_in[9];
    const float* Bu = (const float*)d_in[10];
    const float* Bd = (const float*)d_in[11];

    float* out     = (float*)d_out;
    float* routing = out + (size_t)NTOK * DMODEL;
    float* choice  = routing + NTOK * NEXP;

    void *xp,*wg,*wu,*wd,*hp,*cg,*cu,*cd,*bg,*bu,*bd;
    cudaGetSymbolAddress(&xp, g_x_);
    cudaGetSymbolAddress(&wg, g_wg_); cudaGetSymbolAddress(&wu, g_wu_);
    cudaGetSymbolAddress(&wd, g_wd_); cudaGetSymbolAddress(&hp, g_h_);
    cudaGetSymbolAddress(&cg, g_cg_); cudaGetSymbolAddress(&cu, g_cu_);
    cudaGetSymbolAddress(&cd, g_cd_);
    cudaGetSymbolAddress(&bg, g_bg_); cudaGetSymbolAddress(&bu, g_bu_);
    cudaGetSymbolAddress(&bd, g_bd_);

    PFN_encodeTiled enc = nullptr;
    cudaDriverEntryPointQueryResult qr;
    cudaGetDriverEntryPointByVersion("cuTensorMapEncodeTiled", (void**)&enc,
                                     12000, cudaEnableDefault, &qr);

    static CUtensorMap tmx, tmwg, tmwu, tmwd, tmh, tmcg, tmcu, tmcd, tmbg, tmbu, tmbd;
    make_map(enc, &tmx,  xp, DMODEL, NTOK,   64, 128);
    make_map(enc, &tmwg, wg, DMODEL, MWIDTH, 64, 64);
    make_map(enc, &tmwu, wu, DMODEL, MWIDTH, 64, 64);
    make_map(enc, &tmwd, wd, MWIDTH, DMODEL, 64, 128);
    make_map(enc, &tmh,  hp, MWIDTH, NTOK,   64, 128);
    make_map(enc, &tmcg, cg, ERANK,  NTOK,   64, 128);
    make_map(enc, &tmcu, cu, ERANK,  NTOK,   64, 128);
    make_map(enc, &tmcd, cd, ERANK,  NTOK,   64, 128);
    make_map(enc, &tmbg, bg, ERANK,  MWIDTH, 64, 64);
    make_map(enc, &tmbu, bu, ERANK,  MWIDTH, 64, 64);
    make_map(enc, &tmbd, bd, ERANK,  DMODEL, 64, 128);

    const int n4w = MWIDTH*DMODEL/4;
    k_cvtW<<<dim3((n4w+255)/256, 3), 256>>>(Wg, (h16*)wg, Wu, (h16*)wu, Wd, (h16*)wd, n4w);
    k_bflat<<<dim3(MWIDTH, 3), 128>>>(Bg, (h16*)bg, Bu, (h16*)bu, Bd, (h16*)bd);

    k_router<<<NTOK, 256>>>(x, Wr, br, Ag, Au, routing, choice);  // also writes g_x_ fp16

    const int smem_sz = 3 * 32768 + 1024;   // +1024 for in-kernel 1024-alignment
    cudaFuncSetAttribute(k_mma<true>,  cudaFuncAttributeMaxDynamicSharedMemorySize, smem_sz);
    cudaFuncSetAttribute(k_mma<false>, cudaFuncAttributeMaxDynamicSharedMemorySize, smem_sz);

    // DUAL: grid (m-blocks=32, n-blocks=88)
    k_mma<true><<<dim3(NTOK/128, MWIDTH/64), 256, smem_sz>>>(
        nullptr, tmx, tmwg, tmwu, tmcg, tmcu, tmbg, tmbu);
    k_hd<<<NTOK, 256>>>(Ad, routing);
    // down: grid (n-blocks=16, m-blocks=32)
    k_mma<false><<<dim3(DMODEL/128, NTOK/128), 256, smem_sz>>>(
        out, tmh, tmwd, tmwd, tmcd, tmcd, tmbd, tmbd);
}

// round 17
// speedup vs baseline: 1.0547x; 1.0547x over previous
#include <cuda_runtime.h>
#include <cuda_fp16.h>
#include <cuda.h>
#include <math.h>
#include <stdint.h>

#define NTOK   4096
#define DMODEL 2048
#define MWIDTH 5632
#define NEXP   8
#define RANK   16
#define ERANK  128
#define FSCALE 2.0f

typedef __half h16;

// ---------------- scratch (uint4 => 16B aligned) ----------------
__device__ uint4 g_x_ [(size_t)NTOK*DMODEL/8];                        // x fp16
__device__ uint4 g_wg_[(size_t)MWIDTH*DMODEL/8];
__device__ uint4 g_wu_[(size_t)MWIDTH*DMODEL/8];
__device__ uint4 g_wd_[(size_t)MWIDTH*DMODEL/8];
__device__ uint4 g_h_ [(size_t)NTOK*MWIDTH/8];                        // h fp16
__device__ uint4 g_cg_[NTOK*ERANK/8], g_cu_[NTOK*ERANK/8], g_cd_[NTOK*ERANK/8];
__device__ uint4 g_bg_[MWIDTH*ERANK/8], g_bu_[MWIDTH*ERANK/8];        // flat [n][128]
__device__ uint4 g_bd_[DMODEL*ERANK/8];

// ---------------- helpers ----------------
__device__ __forceinline__ uint32_t s2u(const void* p){
    return (uint32_t)__cvta_generic_to_shared(p);
}
__device__ __forceinline__ uint32_t sw128(uint32_t o){ return o ^ ((o >> 3) & 0x70u); }
__device__ __forceinline__ void mbar_init(uint32_t a, uint32_t cnt){
    asm volatile("mbarrier.init.shared.b64 [%0], %1;" :: "r"(a), "r"(cnt) : "memory");
}
__device__ __forceinline__ void mbar_expect(uint32_t a, uint32_t bytes){
    asm volatile("mbarrier.arrive.expect_tx.shared.b64 _, [%0], %1;"
                 :: "r"(a), "r"(bytes) : "memory");
}
__device__ __forceinline__ void mbar_wait(uint32_t a, uint32_t parity){
    uint32_t done;
    asm volatile("{\n\t.reg .pred p;\n\t"
        "mbarrier.try_wait.parity.acquire.cta.shared::cta.b64 p, [%1], %2;\n\t"
        "selp.b32 %0, 1, 0, p;\n\t}"
        : "=r"(done) : "r"(a), "r"(parity) : "memory");
    if (!done) {
        asm volatile("{\n\t.reg .pred P1;\n\t"
            "W_%=:\n\t"
            "mbarrier.try_wait.parity.acquire.cta.shared::cta.b64 P1, [%0], %1, 0x989680;\n\t"
            "@P1 bra.uni D_%=;\n\t"
            "bra.uni W_%=;\n\t"
            "D_%=:\n\t}"
            :: "r"(a), "r"(parity) : "memory");
    }
}
// 2D TMA tensor copy gmem->smem, completion via mbarrier complete_tx
__device__ __forceinline__ void tma2d(uint32_t dst, const CUtensorMap& tm,
                                      int c0, int c1, uint32_t mbar){
    asm volatile("cp.async.bulk.tensor.2d.shared::cta.global.tile.mbarrier::complete_tx::bytes "
                 "[%0], [%1, {%2, %3}], [%4];"
                 :: "r"(dst), "l"((uint64_t)&tm), "r"(c0), "r"(c1), "r"(mbar) : "memory");
}

#define LDM4(R, A) asm volatile( \
    "ldmatrix.sync.aligned.m8n8.x4.shared.b16 {%0,%1,%2,%3}, [%4];" \
    : "=r"((R)[0]), "=r"((R)[1]), "=r"((R)[2]), "=r"((R)[3]) : "r"(A))

#define MMA(D, A0, A1, A2, A3, B0, B1) asm volatile( \
    "mma.sync.aligned.m16n8k16.row.col.f32.f16.f16.f32 " \
    "{%0,%1,%2,%3}, {%4,%5,%6,%7}, {%8,%9}, {%0,%1,%2,%3};" \
    : "+f"((D)[0]), "+f"((D)[1]), "+f"((D)[2]), "+f"((D)[3]) \
    : "r"(A0), "r"(A1), "r"(A2), "r"(A3), "r"(B0), "r"(B1))

// ---------------- conversion kernels ----------------
__global__ void k_cvtW(const float* __restrict__ i0, h16* __restrict__ o0,
                       const float* __restrict__ i1, h16* __restrict__ o1,
                       const float* __restrict__ i2, h16* __restrict__ o2, int n4){
    const int y = blockIdx.y;
    const float* in = (y == 0) ? i0 : (y == 1) ? i1 : i2;
    h16*         o  = (y == 0) ? o0 : (y == 1) ? o1 : o2;
    int i = blockIdx.x * blockDim.x + threadIdx.x;
    if (i >= n4) return;
    float4 v = ((const float4*)in)[i];
    __half2 p0 = __floats2half2_rn(v.x, v.y);
    __half2 p1 = __floats2half2_rn(v.z, v.w);
    uint2 u{*(uint32_t*)&p0, *(uint32_t*)&p1};
    ((uint2*)o)[i] = u;
}
__global__ void k_bflat(const float* __restrict__ i0, h16* __restrict__ o0,
                        const float* __restrict__ i1, h16* __restrict__ o1,
                        const float* __restrict__ i2, h16* __restrict__ o2){
    const int y = blockIdx.y;
    const float* in = (y == 0) ? i0 : (y == 1) ? i1 : i2;
    h16*         o  = (y == 0) ? o0 : (y == 1) ? o1 : o2;
    const int N = (y == 2) ? DMODEL : MWIDTH;
    const int n = blockIdx.x;
    if (n >= N) return;
    const int j = threadIdx.x;                 // 128 threads
    const int e = j >> 4, r = j & 15;
    o[(size_t)n * ERANK + j] = __float2half_rn(in[((size_t)e * N + n) * RANK + r]);
}

// ---------------- router: 4 tokens per block (weights read once per block) ----
__global__ void k_router(const float* __restrict__ x,  const float* __restrict__ Wr,
                         const float* __restrict__ br, const float* __restrict__ Ag,
                         const float* __restrict__ Au,
                         float* __restrict__ out_routing, float* __restrict__ out_choice)
{
    __shared__ float xs[4][DMODEL];            // 32 KB
    __shared__ float red[40][4];
    __shared__ float routing_s[4][NEXP];

    const int tid = threadIdx.x;
    const int t0  = blockIdx.x * 4;

    // load 4 x rows (fp32) and emit fp16 copies
    for (int i = tid; i < 4 * (DMODEL/4); i += blockDim.x){
        const int tok = i / (DMODEL/4), c = i % (DMODEL/4);
        float4 v = ((const float4*)(x + (size_t)(t0+tok) * DMODEL))[c];
        ((float4*)xs[tok])[c] = v;
        __half2 p0 = __floats2half2_rn(v.x, v.y);
        __half2 p1 = __floats2half2_rn(v.z, v.w);
        uint2 u{*(uint32_t*)&p0, *(uint32_t*)&p1};
        ((uint2*)((h16*)g_x_ + (size_t)(t0+tok) * DMODEL))[c] = u;
    }
    __syncthreads();

    const int w = tid >> 5, lane = tid & 31;
    #pragma unroll
    for (int q = 0; q < 5; ++q) {
        const int o = w + 8*q;
        const float* wrow = (o < 8)  ? (Wr + o*DMODEL)
                          : (o < 24) ? (Ag + (o-8)*DMODEL)
                                     : (Au + (o-24)*DMODEL);
        float a0 = 0.f, a1 = 0.f, a2 = 0.f, a3 = 0.f;
        for (int k = lane; k < DMODEL; k += 32){
            const float wv = wrow[k];
            a0 = fmaf(xs[0][k], wv, a0);
            a1 = fmaf(xs[1][k], wv, a1);
            a2 = fmaf(xs[2][k], wv, a2);
            a3 = fmaf(xs[3][k], wv, a3);
        }
        #pragma unroll
        for (int off = 16; off; off >>= 1){
            a0 += __shfl_xor_sync(0xffffffffu, a0, off);
            a1 += __shfl_xor_sync(0xffffffffu, a1, off);
            a2 += __shfl_xor_sync(0xffffffffu, a2, off);
            a3 += __shfl_xor_sync(0xffffffffu, a3, off);
        }
        if (lane == 0){ red[o][0]=a0; red[o][1]=a1; red[o][2]=a2; red[o][3]=a3; }
    }
    __syncthreads();

    if (tid < 4){
        const int tok = tid, t = t0 + tok;
        float lg[NEXP]; float mx = -1e30f;
        #pragma unroll
        for (int e = 0; e < NEXP; ++e){ lg[e] = red[e][tok] + br[e]; mx = fmaxf(mx, lg[e]); }
        float sum = 0.f;
        #pragma unroll
        for (int e = 0; e < NEXP; ++e){ lg[e] = expf(lg[e]-mx); sum += lg[e]; }
        const float inv = 1.f/sum;
        int am = 0; float best = -1.f;
        #pragma unroll
        for (int e = 0; e < NEXP; ++e){
            const float r = lg[e]*inv; routing_s[tok][e] = r;
            if (r > best){ best = r; am = e; }
        }
        #pragma unroll
        for (int e = 0; e < NEXP; ++e){
            const float r = routing_s[tok][e];
            out_routing[t*NEXP + e] = r;
            const float yh = (e == am) ? 1.f : 0.f;
            out_choice[t*NEXP + e] = (yh - r) + r;
        }
    }
    __syncthreads();

    // c_g / c_u : 4 tokens x 256 values
    for (int idx = tid; idx < 1024; idx += blockDim.x){
        const int tok = idx >> 8, j = idx & 255;
        const int t = t0 + tok;
        if (j < 128){
            const int e = j >> 4, rr = j & 15;
            ((h16*)g_cg_)[(size_t)t*ERANK + j]
                = __float2half_rn(routing_s[tok][e] * red[8 + rr][tok] * FSCALE);
        } else {
            const int jj = j - 128, e = jj >> 4, rr = jj & 15;
            ((h16*)g_cu_)[(size_t)t*ERANK + jj]
                = __float2half_rn(routing_s[tok][e] * red[24 + rr][tok] * FSCALE);
        }
    }
}

// ---------------- h @ Ad^T -> c_d : 4 tokens per block ----------------
__global__ void k_hd(const float* __restrict__ Ad, const float* __restrict__ routing)
{
    __shared__ h16   hs[4][MWIDTH];            // 45 KB (raw fp16)
    __shared__ float red[RANK][4];

    const int tid = threadIdx.x;
    const int t0  = blockIdx.x * 4;
    // copy 4 h rows (fp16, raw uint4)
    for (int i = tid; i < 4 * (MWIDTH/8); i += blockDim.x){
        const int tok = i / (MWIDTH/8), c = i % (MWIDTH/8);
        ((uint4*)hs[tok])[c] =
            ((const uint4*)((const h16*)g_h_ + (size_t)(t0+tok) * MWIDTH))[c];
    }
    __syncthreads();

    const int w = tid >> 5, lane = tid & 31;
    #pragma unroll
    for (int q = 0; q < 2; ++q) {
        const int r = w*2 + q;
        const float* arow = Ad + (size_t)r * MWIDTH;
        float a0 = 0.f, a1 = 0.f, a2 = 0.f, a3 = 0.f;
        for (int k = lane; k < MWIDTH; k += 32){
            const float av = arow[k];
            a0 = fmaf(__half2float(hs[0][k]), av, a0);
            a1 = fmaf(__half2float(hs[1][k]), av, a1);
            a2 = fmaf(__half2float(hs[2][k]), av, a2);
            a3 = fmaf(__half2float(hs[3][k]), av, a3);
        }
        #pragma unroll
        for (int off = 16; off; off >>= 1){
            a0 += __shfl_xor_sync(0xffffffffu, a0, off);
            a1 += __shfl_xor_sync(0xffffffffu, a1, off);
            a2 += __shfl_xor_sync(0xffffffffu, a2, off);
            a3 += __shfl_xor_sync(0xffffffffu, a3, off);
        }
        if (lane == 0){ red[r][0]=a0; red[r][1]=a1; red[r][2]=a2; red[r][3]=a3; }
    }
    __syncthreads();

    for (int idx = tid; idx < 512; idx += blockDim.x){
        const int tok = idx >> 7, j = idx & 127;
        const int t = t0 + tok;
        const int e = j >> 4, rr = j & 15;
        ((h16*)g_cd_)[(size_t)t*ERANK + j]
            = __float2half_rn(routing[t*NEXP + e] * red[rr][tok] * FSCALE);
    }
}

// ---------------- fp16 mma.sync GEMM, 2D-TMA loads, 2 CTAs/SM ----------------
// Swizzled ldmatrix addresses hoisted: sw128(o0 | kb) == sw128(o0) ^ kb for
// kb in bits 5-6 (swizzle XOR source is bits 7-9, untouched by kb).
// DUAL : BM=128 BN=64,  A=x,  B0=Wg->accG, B1=Wu->accU (+aug cg/Bg, cu/Bu),
//        epilogue silu(g)*u -> g_h_ (fp16)
// !DUAL: BM=128 BN=128, A=h,  B0=Wd (+aug cd/Bd), epilogue -> fp32 out
template<bool DUAL>
__global__ __launch_bounds__(256, 2)
void k_mma(float* __restrict__ OutP,
           const __grid_constant__ CUtensorMap tmA,
           const __grid_constant__ CUtensorMap tmB0,
           const __grid_constant__ CUtensorMap tmB1,
           const __grid_constant__ CUtensorMap tmCA,
           const __grid_constant__ CUtensorMap tmCA2,
           const __grid_constant__ CUtensorMap tmBA,
           const __grid_constant__ CUtensorMap tmBA2)
{
    constexpr int PA     = 16384;                       // A plane: 128 rows x 128B
    constexpr int BN     = DUAL ? 64 : 128;
    constexpr int PB     = BN * 128;                    // 8192 / 16384
    constexpr int STAGEB = PA + (DUAL ? 2 : 1) * PB;    // 32768 both
    constexpr int JN     = DUAL ? 4 : 8;
    constexpr int JH     = JN / 2;
    constexpr int WTN    = DUAL ? 32 : 64;
    constexpr int NKM    = DUAL ? (DMODEL/64) : (MWIDTH/64);  // 32 / 88
    constexpr int NT     = DUAL ? (NKM + 4) : (NKM + 2);

    __shared__ __align__(8) uint64_t mbs[3];
    extern __shared__ __align__(16) char smem[];
    const uint32_t sb  = (s2u(smem) + 1023u) & ~1023u;   // 1024-align for SW128 atoms
    const uint32_t mbb = s2u(mbs);
    const int tid = threadIdx.x, wid = tid >> 5, lane = tid & 31;
    const int wm = wid & 3, wn = wid >> 2;
    const int m0 = (DUAL ? blockIdx.x : blockIdx.y) * 128;
    const int n0 = (DUAL ? blockIdx.y : blockIdx.x) * BN;

    if (tid < 3) mbar_init(mbb + tid*8, 1);
    __syncthreads();

    float accG[2][JN][4];
    float accU[DUAL?2:1][DUAL?JN:1][4];
    #pragma unroll
    for (int m=0;m<2;++m) for (int j=0;j<JN;++j) for (int q=0;q<4;++q) accG[m][j][q]=0.f;
    if constexpr (DUAL){
        #pragma unroll
        for (int m=0;m<2;++m) for (int j=0;j<JN;++j) for (int q=0;q<4;++q) accU[m][j][q]=0.f;
    }

    // hoisted swizzled base offsets (kb folded in later by XOR)
    const uint32_t lanehi = (uint32_t)((lane >> 4) << 4);
    const uint32_t offA0 = sw128((uint32_t)((wm*32      + (lane & 15)) * 128) + lanehi);
    const uint32_t offA1 = sw128((uint32_t)((wm*32 + 16 + (lane & 15)) * 128) + lanehi);
    uint32_t offB[JH];
    #pragma unroll
    for (int g = 0; g < JH; ++g)
        offB[g] = sw128((uint32_t)((wn*WTN + g*16 + (lane & 15)) * 128) + lanehi);

    // single-thread tile load: expect_tx + 2-3 TMA 2D requests
    auto load_tile = [&](int kt){
        const uint32_t st  = sb  + (uint32_t)(kt % 3) * STAGEB;
        const uint32_t mb_ = mbb + (uint32_t)(kt % 3) * 8;
        if (kt < NKM){
            const int ko = kt * 64;
            mbar_expect(mb_, (uint32_t)STAGEB);
            tma2d(st,       tmA,  ko, m0, mb_);
            tma2d(st + PA,  tmB0, ko, n0, mb_);
            if constexpr (DUAL) tma2d(st + PA + PB, tmB1, ko, n0, mb_);
        } else {
            const bool gsel = !DUAL || (kt < NKM + 2);
            const int ko = (kt - NKM - ((DUAL && !gsel) ? 2 : 0)) * 64;
            mbar_expect(mb_, (uint32_t)(PA + PB));
            tma2d(st,      gsel ? tmCA : tmCA2, ko, m0, mb_);
            tma2d(st + PA, gsel ? tmBA : tmBA2, ko, n0, mb_);
        }
    };

    if (tid == 0){ load_tile(0); load_tile(1); }

    for (int kt = 0; kt < NT; ++kt){
        mbar_wait(mbb + (uint32_t)(kt % 3)*8, (kt/3) & 1);   // tile kt landed
        __syncthreads();                     // all warps done reading stage (kt-1)%3
        if (kt + 2 < NT && tid == 0) load_tile(kt + 2);

        const uint32_t st = sb + (uint32_t)(kt % 3) * STAGEB;
        const uint32_t bA0 = st + offA0, bA1 = st + offA1;
        uint32_t bB0[JH], bB1[DUAL ? JH : 1];
        #pragma unroll
        for (int g = 0; g < JH; ++g) bB0[g] = st + PA + offB[g];
        if constexpr (DUAL){
            #pragma unroll
            for (int g = 0; g < JH; ++g) bB1[g] = st + PA + PB + offB[g];
        }
        // mode: 0 main, 1 aug->accG, 2 aug->accU
        int mode = 0;
        if (kt >= NKM) mode = (DUAL && kt >= NKM+2) ? 2 : 1;

        #pragma unroll
        for (int ks = 0; ks < 4; ++ks){
            const uint32_t kb = (uint32_t)(ks * 32);
            uint32_t a0[4], a1[4], bb[JH][4];
            LDM4(a0, bA0 ^ kb);
            LDM4(a1, bA1 ^ kb);
            #pragma unroll
            for (int g = 0; g < JH; ++g) LDM4(bb[g], bB0[g] ^ kb);

            if (mode != 2){
                #pragma unroll
                for (int j = 0; j < JN; ++j){
                    const uint32_t bx = bb[j>>1][j&1], by = bb[j>>1][(j&1)+2];
                    MMA(accG[0][j], a0[0],a0[1],a0[2],a0[3], bx, by);
                    MMA(accG[1][j], a1[0],a1[1],a1[2],a1[3], bx, by);
                }
            } else {
                #pragma unroll
                for (int j = 0; j < JN; ++j){
                    const uint32_t bx = bb[j>>1][j&1], by = bb[j>>1][(j&1)+2];
                    MMA(accU[0][j], a0[0],a0[1],a0[2],a0[3], bx, by);
                    MMA(accU[1][j], a1[0],a1[1],a1[2],a1[3], bx, by);
                }
            }
            if constexpr (DUAL){
                if (mode == 0){
                    #pragma unroll
                    for (int g = 0; g < JH; ++g) LDM4(bb[g], bB1[g] ^ kb);
                    #pragma unroll
                    for (int j = 0; j < JN; ++j){
                        const uint32_t bx = bb[j>>1][j&1], by = bb[j>>1][(j&1)+2];
                        MMA(accU[0][j], a0[0],a0[1],a0[2],a0[3], bx, by);
                        MMA(accU[1][j], a1[0],a1[1],a1[2],a1[3], bx, by);
                    }
                }
            }
        }
    }

    // ---------------- epilogue ----------------
    #pragma unroll
    for (int m = 0; m < 2; ++m){
        #pragma unroll
        for (int j = 0; j < JN; ++j){
            const int r0 = m0 + wm*32 + m*16 + (lane >> 2);
            const int c0 = n0 + wn*WTN + j*8 + (lane & 3)*2;
            if constexpr (DUAL){
                h16* gh = (h16*)g_h_;
                float hv[4];
                #pragma unroll
                for (int q = 0; q < 4; ++q){
                    const float g = accG[m][j][q], u = accU[m][j][q];
                    hv[q] = g * u / (1.f + __expf(-g));
                }
                *(__half2*)(gh + (size_t)r0*MWIDTH + c0)     = __floats2half2_rn(hv[0], hv[1]);
                *(__half2*)(gh + (size_t)(r0+8)*MWIDTH + c0) = __floats2half2_rn(hv[2], hv[3]);
            } else {
                *(float2*)(OutP + (size_t)r0*DMODEL + c0)
                    = make_float2(accG[m][j][0], accG[m][j][1]);
                *(float2*)(OutP + (size_t)(r0+8)*DMODEL + c0)
                    = make_float2(accG[m][j][2], accG[m][j][3]);
            }
        }
    }
}

// ---------------------------------------------------------------------------
typedef CUresult (*PFN_encodeTiled)(CUtensorMap*, CUtensorMapDataType, cuuint32_t,
    void*, const cuuint64_t*, const cuuint64_t*, const cuuint32_t*, const cuuint32_t*,
    CUtensorMapInterleave, CUtensorMapSwizzle, CUtensorMapL2promotion,
    CUtensorMapFloatOOBfill);

static void make_map(PFN_encodeTiled enc, CUtensorMap* tm, void* base,
                     uint64_t d0, uint64_t d1, uint32_t b0, uint32_t b1){
    cuuint64_t dims[2]    = {d0, d1};
    cuuint64_t strides[1] = {d0 * 2};          // row stride in bytes (fp16)
    cuuint32_t box[2]     = {b0, b1};
    cuuint32_t es[2]      = {1, 1};
    enc(tm, CU_TENSOR_MAP_DATA_TYPE_FLOAT16, 2, base, dims, strides, box, es,
        CU_TENSOR_MAP_INTERLEAVE_NONE, CU_TENSOR_MAP_SWIZZLE_128B,
        CU_TENSOR_MAP_L2_PROMOTION_L2_128B, CU_TENSOR_MAP_FLOAT_OOB_FILL_NONE);
}

extern "C" void kernel_launch(void* const* d_in, const int* in_sizes, int n_in,
                              void* d_out, int out_size)
{
    const float* x  = (const float*)d_in[0];
    const float* Wr = (const float*)d_in[1];
    const float* br = (const float*)d_in[2];
    const float* Wg = (const float*)d_in[3];
    const float* Wu = (const float*)d_in[4];
    const float* Wd = (const float*)d_in[5];
    const float* Ag = (const float*)d_in[6];
    const float* Au = (const float*)d_in[7];
    const float* Ad = (const float*)d_in[8];
    const float* Bg = (const float*)d_in[9];
    const float* Bu = (const float*)d_in[10];
    const float* Bd = (const float*)d_in[11];

    float* out     = (float*)d_out;
    float* routing = out + (size_t)NTOK * DMODEL;
    float* choice  = routing + NTOK * NEXP;

    void *xp,*wg,*wu,*wd,*hp,*cg,*cu,*cd,*bg,*bu,*bd;
    cudaGetSymbolAddress(&xp, g_x_);
    cudaGetSymbolAddress(&wg, g_wg_); cudaGetSymbolAddress(&wu, g_wu_);
    cudaGetSymbolAddress(&wd, g_wd_); cudaGetSymbolAddress(&hp, g_h_);
    cudaGetSymbolAddress(&cg, g_cg_); cudaGetSymbolAddress(&cu, g_cu_);
    cudaGetSymbolAddress(&cd, g_cd_);
    cudaGetSymbolAddress(&bg, g_bg_); cudaGetSymbolAddress(&bu, g_bu_);
    cudaGetSymbolAddress(&bd, g_bd_);

    PFN_encodeTiled enc = nullptr;
    cudaDriverEntryPointQueryResult qr;
    cudaGetDriverEntryPointByVersion("cuTensorMapEncodeTiled", (void**)&enc,
                                     12000, cudaEnableDefault, &qr);

    static CUtensorMap tmx, tmwg, tmwu, tmwd, tmh, tmcg, tmcu, tmcd, tmbg, tmbu, tmbd;
    make_map(enc, &tmx,  xp, DMODEL, NTOK,   64, 128);
    make_map(enc, &tmwg, wg, DMODEL, MWIDTH, 64, 64);
    make_map(enc, &tmwu, wu, DMODEL, MWIDTH, 64, 64);
    make_map(enc, &tmwd, wd, MWIDTH, DMODEL, 64, 128);
    make_map(enc, &tmh,  hp, MWIDTH, NTOK,   64, 128);
    make_map(enc, &tmcg, cg, ERANK,  NTOK,   64, 128);
    make_map(enc, &tmcu, cu, ERANK,  NTOK,   64, 128);
    make_map(enc, &tmcd, cd, ERANK,  NTOK,   64, 128);
    make_map(enc, &tmbg, bg, ERANK,  MWIDTH, 64, 64);
    make_map(enc, &tmbu, bu, ERANK,  MWIDTH, 64, 64);
    make_map(enc, &tmbd, bd, ERANK,  DMODEL, 64, 128);

    const int n4w = MWIDTH*DMODEL/4;
    k_cvtW<<<dim3((n4w+255)/256, 3), 256>>>(Wg, (h16*)wg, Wu, (h16*)wu, Wd, (h16*)wd, n4w);
    k_bflat<<<dim3(MWIDTH, 3), 128>>>(Bg, (h16*)bg, Bu, (h16*)bu, Bd, (h16*)bd);

    // router: 4 tokens/block (also writes g_x_ fp16)
    k_router<<<NTOK/4, 256>>>(x, Wr, br, Ag, Au, routing, choice);

    const int smem_sz = 3 * 32768 + 1024;   // +1024 for in-kernel 1024-alignment
    cudaFuncSetAttribute(k_mma<true>,  cudaFuncAttributeMaxDynamicSharedMemorySize, smem_sz);
    cudaFuncSetAttribute(k_mma<false>, cudaFuncAttributeMaxDynamicSharedMemorySize, smem_sz);

    // DUAL: grid (m-blocks=32, n-blocks=88)
    k_mma<true><<<dim3(NTOK/128, MWIDTH/64), 256, smem_sz>>>(
        nullptr, tmx, tmwg, tmwu, tmcg, tmcu, tmbg, tmbu);
    // c_d: 4 tokens/block
    k_hd<<<NTOK/4, 256>>>(Ad, routing);
    // down: grid (n-blocks=16, m-blocks=32)
    k_mma<false><<<dim3(DMODEL/128, NTOK/128), 256, smem_sz>>>(
        out, tmh, tmwd, tmwd, tmcd, tmcd, tmbd, tmbd);
}